// round 9
// baseline (speedup 1.0000x reference)
#include <cuda_runtime.h>
#include <math.h>

#define N_VARS 64
#define NV1    65      // N = n_vars + 1
#define M_CL   256
#define KD     12
#define CST    72      // padded C row stride in floats (cols 65..71 zero)
#define HALF   36      // n-range width per lane-half
#define NP     18      // f32x2 pairs per half

// Gram matrix C = Sw^T Sw with ZEROED DIAGONAL, padded rows
__device__ __align__(16) float g_C[NV1 * CST];

typedef unsigned long long u64;

// ---- packed f32x2 primitives (pure PTX, operands stay in u64 pairs) --------
__device__ __forceinline__ u64 ffma2u(u64 a, u64 b, u64 c)
{
    u64 d;
    asm("fma.rn.f32x2 %0, %1, %2, %3;" : "=l"(d) : "l"(a), "l"(b), "l"(c));
    return d;
}
__device__ __forceinline__ u64 fadd2u(u64 a, u64 b)
{
    u64 d;
    asm("add.rn.f32x2 %0, %1, %2;" : "=l"(d) : "l"(a), "l"(b));
    return d;
}
__device__ __forceinline__ u64 pack2(float x, float y)
{
    u64 d;
    asm("mov.b64 %0, {%1, %2};" : "=l"(d) : "f"(x), "f"(y));
    return d;
}
__device__ __forceinline__ void unpack2(u64 p, float& x, float& y)
{
    asm("mov.b64 {%0, %1}, %2;" : "=f"(x), "=f"(y) : "l"(p));
}

// packed dot of a preloaded 36-wide C-row half with packed V
__device__ __forceinline__ float dot_regs(const ulonglong2 w[9],
                                          const u64* __restrict__ Vp)
{
    u64 a0 = 0ull, a1 = 0ull, a2 = 0ull, a3 = 0ull;
#pragma unroll
    for (int c = 0; c < 9; ++c) {
        if (c & 1) { a2 = ffma2u(w[c].x, Vp[2*c+0], a2); a3 = ffma2u(w[c].y, Vp[2*c+1], a3); }
        else       { a0 = ffma2u(w[c].x, Vp[2*c+0], a0); a1 = ffma2u(w[c].y, Vp[2*c+1], a1); }
    }
    const u64 tt = fadd2u(fadd2u(a0, a2), fadd2u(a1, a3));
    float x, y; unpack2(tt, x, y);
    return x + y;
}

// ---------------------------------------------------------------------------
// Kernel 1: C[i][j] = sum_m (S[m,i]*w[m]) * (S[m,j]*w[m]);  C[i][i] = 0
// ---------------------------------------------------------------------------
__global__ void gram_kernel(const float* __restrict__ S, const float* __restrict__ w)
{
    const int i = blockIdx.x;    // 0..64
    const int j = threadIdx.x;   // 0..71
    float acc = 0.f;
    if (j < NV1) {
#pragma unroll 16
        for (int m = 0; m < M_CL; ++m) {
            const float wm = __ldg(&w[m]);
            acc = fmaf(__ldg(&S[m * NV1 + i]) * wm, __ldg(&S[m * NV1 + j]) * wm, acc);
        }
    }
    g_C[i * CST + j] = (j < NV1 && j != i) ? acc : 0.f;
}

// ---------------------------------------------------------------------------
// Kernel 2: pipelined coordinate descent, TWO batches interleaved per warp.
// Lane = h*16 + k, k in [0,12) active, h in {0,1}.
// Per batch, lane (h,k) holds V[k][n] for n in [36h,36h+36) as 18 f32x2 regs.
// Batches A,B alternate in the instruction stream; C-row loads are shared.
// Per-batch recurrence (R5 scheme): g = fma(t, inv, P), P precomputed with
// old slot removed; norm reduce; rsqrt; commit.
// ---------------------------------------------------------------------------
__device__ __forceinline__ void init_V(const float* __restrict__ z,
                                       const float* __restrict__ r,
                                       int b, int k, int h, u64* Vp)
{
    const unsigned FULL = 0xffffffffu;
    const float PI = 3.14159265358979323846f;
#pragma unroll
    for (int jp = 0; jp < NP; ++jp) {
        float vv[2];
#pragma unroll
        for (int q = 0; q < 2; ++q) {
            const int j  = 2 * jp + q;
            const int n  = HALF * h + j;
            const int nc = (n < 1) ? 1 : ((n > 64) ? 64 : n);
            const float zv = z[b * N_VARS + nc - 1];
            const float rv = r[(b * N_VARS + nc - 1) * KD + ((k < KD) ? k : 0)];
            const float rp = (k >= 1 && k < KD) ? rv : 0.f;
            float s = rp * rp;
            s += __shfl_xor_sync(FULL, s, 8);
            s += __shfl_xor_sync(FULL, s, 4);
            s += __shfl_xor_sync(FULL, s, 2);
            s += __shfl_xor_sync(FULL, s, 1);
            const float inv0 = (s > 1e-16f) ? rsqrtf(s) : 1e8f;
            float sn, cs;
            __sincosf(PI * zv, &sn, &cs);
            float v = sn * (rp * inv0);
            if (k == 0) v -= cs;
            const bool active = (n >= 1 && n <= 64);
            vv[q] = active ? v : ((n == 0) ? ((k == 0) ? 1.f : 0.f) : 0.f);
        }
        Vp[jp] = pack2(vv[0], vv[1]);
    }
}

__global__ void __launch_bounds__(128, 1)
mix_kernel(const float* __restrict__ z, const float* __restrict__ r,
           const int* __restrict__ miter_p, float* __restrict__ out, int B)
{
    __shared__ __align__(16) float Csh[NV1 * CST];   // 18,720 B
    {
        const float4* src = (const float4*)g_C;
        float4* dst = (float4*)Csh;
#pragma unroll 4
        for (int t = threadIdx.x; t < (NV1 * CST) / 4; t += 128) dst[t] = src[t];
    }
    __syncthreads();

    const int lane = threadIdx.x & 31;
    const int warp = threadIdx.x >> 5;
    const int wgid = blockIdx.x * 4 + warp;       // global warp id
    int bA = wgid * 2;
    int bB = wgid * 2 + 1;
    if (bA >= B) return;
    if (bB >= B) bB = bA;                          // harmless duplicate on odd B

    const int k = lane & 15;      // component index (0..11 active)
    const int h = lane >> 4;      // which n-half
    const unsigned FULL = 0xffffffffu;
    const float PI = 3.14159265358979323846f;
    const int miter = miter_p ? *miter_p : 12;

    u64 VA[NP], VB[NP];
    init_V(z, r, bA, k, h, VA);
    init_V(z, r, bB, k, h, VB);

    // ---- prologue: P = full dot of row 1 for both batches ----
    float PA, PB;
    {
        const ulonglong2* cr = (const ulonglong2*)(Csh + 1 * CST + HALF * h);
        ulonglong2 w[9];
#pragma unroll
        for (int c = 0; c < 9; ++c) w[c] = cr[c];
        const float aA = dot_regs(w, VA);
        const float aB = dot_regs(w, VB);
        PA = aA + __shfl_xor_sync(FULL, aA, 16);
        PB = aB + __shfl_xor_sync(FULL, aB, 16);
    }
    float tA = 0.f, invA = 0.f, tB = 0.f, invB = 0.f;

    // ---- interleaved sweeps ----
    for (int it = 0; it < miter; ++it) {
#pragma unroll
        for (int i = 1; i < NV1; ++i) {
            const int hi = (i < HALF) ? 0 : 1;    // owning half of coord i
            const int ji = i - HALF * hi;         // element slot in owner
            const int jp = ji >> 1;               // packed slot (compile-time)
            const int inext = (i < 64) ? i + 1 : 1;

            // shared row loads (serve both batches)
            const float cni = Csh[inext * CST + i];
            const ulonglong2* cr = (const ulonglong2*)(Csh + inext * CST + HALF * h);
            ulonglong2 w[9];
#pragma unroll
            for (int c = 0; c < 9; ++c) w[c] = cr[c];

            // -------- chains: g for both batches --------
            const float gA = fmaf(tA, invA, PA);
            const float gB = fmaf(tB, invB, PB);

            // -------- norm reductions (independent, interleave) --------
            const float cA1 = __shfl_xor_sync(FULL, gA, 4);
            const float cB1 = __shfl_xor_sync(FULL, gB, 4);
            const float cA2 = __shfl_xor_sync(FULL, gA, 8);
            const float cB2 = __shfl_xor_sync(FULL, gB, 8);
            const float cA3 = __shfl_xor_sync(FULL, gA, 12);
            const float cB3 = __shfl_xor_sync(FULL, gB, 12);
            float sA = gA * gA, sB = gB * gB;
            sA = fmaf(cA1, cA1, sA);  sB = fmaf(cB1, cB1, sB);
            sA = fmaf(cA2, cA2, sA);  sB = fmaf(cB2, cB2, sB);
            sA = fmaf(cA3, cA3, sA);  sB = fmaf(cB3, cB3, sB);
            const float dA1 = __shfl_xor_sync(FULL, sA, 1);
            const float dB1 = __shfl_xor_sync(FULL, sB, 1);
            const float dA2 = __shfl_xor_sync(FULL, sA, 2);
            const float dB2 = __shfl_xor_sync(FULL, sB, 2);
            const float dA3 = __shfl_xor_sync(FULL, sA, 3);
            const float dB3 = __shfl_xor_sync(FULL, sB, 3);
            float ssA = (sA + dA1) + (dA2 + dA3);
            float ssB = (sB + dB1) + (dB2 + dB3);
            ssA = fmaxf(ssA, 1e-16f);
            ssB = fmaxf(ssB, 1e-16f);

            // -------- pending coeffs --------
            tA = -cni * gA;
            tB = -cni * gB;

            // -------- next-row dots (off-chain) --------
            float accA = dot_regs(w, VA);
            float accB = dot_regs(w, VB);

            float vxA, vyA, vxB, vyB;
            if (h == hi) {
                unpack2(VA[jp], vxA, vyA);
                unpack2(VB[jp], vxB, vyB);
                const float voA = (ji & 1) ? vyA : vxA;
                const float voB = (ji & 1) ? vyB : vxB;
                accA = fmaf(-cni, voA, accA);     // remove OLD V[i]
                accB = fmaf(-cni, voB, accB);
            }
            PA = accA + __shfl_xor_sync(FULL, accA, 16);
            PB = accB + __shfl_xor_sync(FULL, accB, 16);

            // -------- finish chains, commit --------
            invA = rsqrtf(ssA);
            invB = rsqrtf(ssB);
            const float vA = -gA * invA;
            const float vB = -gB * invB;
            if (h == hi) {
                if (ji & 1) { VA[jp] = pack2(vxA, vA); VB[jp] = pack2(vxB, vB); }
                else        { VA[jp] = pack2(vA, vyA); VB[jp] = pack2(vB, vyB); }
            }
        }
    }

    // ---- output: out[b][n-1] = acos(clip(-V[0][n])) / pi ----
    if (k == 0) {
#pragma unroll
        for (int jp = 0; jp < NP; ++jp) {
            float aA[2], aB[2];
            unpack2(VA[jp], aA[0], aA[1]);
            unpack2(VB[jp], aB[0], aB[1]);
#pragma unroll
            for (int q = 0; q < 2; ++q) {
                const int n = HALF * h + 2 * jp + q;
                if (n >= 1 && n <= 64) {
                    float cA = fminf(fmaxf(-aA[q], -1.f + 1e-6f), 1.f - 1e-6f);
                    float cB = fminf(fmaxf(-aB[q], -1.f + 1e-6f), 1.f - 1e-6f);
                    out[bA * N_VARS + (n - 1)] = acosf(cA) * (1.0f / PI);
                    out[bB * N_VARS + (n - 1)] = acosf(cB) * (1.0f / PI);
                }
            }
        }
    }
}

// ---------------------------------------------------------------------------
extern "C" void kernel_launch(void* const* d_in, const int* in_sizes, int n_in,
                              void* d_out, int out_size)
{
    const float* z = (const float*)d_in[0];
    const float* S = (const float*)d_in[1];
    const float* w = (const float*)d_in[2];
    const float* r = (const float*)d_in[3];
    const int* mi  = (n_in > 4) ? (const int*)d_in[4] : nullptr;
    float* out = (float*)d_out;

    const int B = in_sizes[0] / N_VARS;

    gram_kernel<<<NV1, CST>>>(S, w);
    // 2 batches per warp, 4 warps per CTA -> 8 batches per CTA
    mix_kernel<<<(B + 7) / 8, 128>>>(z, r, mi, out, B);
}

// round 10
// speedup vs baseline: 1.4412x; 1.4412x over previous
#include <cuda_runtime.h>
#include <math.h>

#define N_VARS 64
#define NV1    65      // N = n_vars + 1
#define M_CL   256
#define KD     12
#define CST    72      // padded C row stride in floats (cols 65..71 zero)
#define HALF   36      // n-range width per lane-half
#define NP     18      // f32x2 pairs per half

// Gram matrix C = Sw^T Sw with ZEROED DIAGONAL, padded rows
__device__ __align__(16) float g_C[NV1 * CST];

typedef unsigned long long u64;

// ---- packed f32x2 primitives (pure PTX, operands stay in u64 pairs) --------
__device__ __forceinline__ u64 ffma2u(u64 a, u64 b, u64 c)
{
    u64 d;
    asm("fma.rn.f32x2 %0, %1, %2, %3;" : "=l"(d) : "l"(a), "l"(b), "l"(c));
    return d;
}
__device__ __forceinline__ u64 fadd2u(u64 a, u64 b)
{
    u64 d;
    asm("add.rn.f32x2 %0, %1, %2;" : "=l"(d) : "l"(a), "l"(b));
    return d;
}
__device__ __forceinline__ u64 pack2(float x, float y)
{
    u64 d;
    asm("mov.b64 %0, {%1, %2};" : "=l"(d) : "f"(x), "f"(y));
    return d;
}
__device__ __forceinline__ void unpack2(u64 p, float& x, float& y)
{
    asm("mov.b64 {%0, %1}, %2;" : "=f"(x), "=f"(y) : "l"(p));
}

// packed dot of a register-resident 36-wide C-row half with packed V
__device__ __forceinline__ float dot_regs(const ulonglong2 w[9],
                                          const u64* __restrict__ Vp)
{
    u64 a0 = 0ull, a1 = 0ull, a2 = 0ull, a3 = 0ull;
#pragma unroll
    for (int c = 0; c < 9; ++c) {
        if (c & 1) { a2 = ffma2u(w[c].x, Vp[2*c+0], a2); a3 = ffma2u(w[c].y, Vp[2*c+1], a3); }
        else       { a0 = ffma2u(w[c].x, Vp[2*c+0], a0); a1 = ffma2u(w[c].y, Vp[2*c+1], a1); }
    }
    const u64 tt = fadd2u(fadd2u(a0, a2), fadd2u(a1, a3));
    float x, y; unpack2(tt, x, y);
    return x + y;
}

// ---------------------------------------------------------------------------
// Kernel 1: C[i][j] = sum_m (S[m,i]*w[m]) * (S[m,j]*w[m]);  C[i][i] = 0
// ---------------------------------------------------------------------------
__global__ void gram_kernel(const float* __restrict__ S, const float* __restrict__ w)
{
    const int i = blockIdx.x;    // 0..64
    const int j = threadIdx.x;   // 0..71
    float acc = 0.f;
    if (j < NV1) {
#pragma unroll 16
        for (int m = 0; m < M_CL; ++m) {
            const float wm = __ldg(&w[m]);
            acc = fmaf(__ldg(&S[m * NV1 + i]) * wm, __ldg(&S[m * NV1 + j]) * wm, acc);
        }
    }
    g_C[i * CST + j] = (j < NV1 && j != i) ? acc : 0.f;
}

// ---------------------------------------------------------------------------
// Kernel 2: pipelined coordinate descent with 1-step ROW PREFETCH.
// One warp per batch (R5 layout). Lane = h*16 + k, k in [0,12) active.
// Lane (h,k) holds V[k][n] for n in [36h,36h+36) as 18 packed f32x2 regs.
// Step i: (1) issue LDS for row i+2 (consumed next step), (2) norm-reduce g,
// (3) dot with row i+1 preloaded LAST step (registers ready, no LDS stall),
// (4) rsqrt + commit. Recurrence: g = fma(t, inv, P).
// ---------------------------------------------------------------------------
__global__ void __launch_bounds__(128, 1)
mix_kernel(const float* __restrict__ z, const float* __restrict__ r,
           const int* __restrict__ miter_p, float* __restrict__ out, int B)
{
    __shared__ __align__(16) float Csh[NV1 * CST];   // 18,720 B
    {
        const float4* src = (const float4*)g_C;
        float4* dst = (float4*)Csh;
#pragma unroll 4
        for (int t = threadIdx.x; t < (NV1 * CST) / 4; t += 128) dst[t] = src[t];
    }
    __syncthreads();

    const int lane = threadIdx.x & 31;
    const int warp = threadIdx.x >> 5;
    const int b    = blockIdx.x * 4 + warp;
    if (b >= B) return;

    const int k = lane & 15;      // component index (0..11 active)
    const int h = lane >> 4;      // which n-half
    const unsigned FULL = 0xffffffffu;
    const float PI = 3.14159265358979323846f;
    const int miter = miter_p ? *miter_p : 12;

    u64 Vp[NP];                   // packed V: pair jp = (n=36h+2jp, n+1)

    // ---- init: V[0]=e0; V[n] = -cos(pi z)e0 + sin(pi z) r_perp_hat ----
#pragma unroll
    for (int jp = 0; jp < NP; ++jp) {
        float vv[2];
#pragma unroll
        for (int q = 0; q < 2; ++q) {
            const int j  = 2 * jp + q;
            const int n  = HALF * h + j;
            const int nc = (n < 1) ? 1 : ((n > 64) ? 64 : n);
            const float zv = z[b * N_VARS + nc - 1];
            const float rv = r[(b * N_VARS + nc - 1) * KD + ((k < KD) ? k : 0)];
            const float rp = (k >= 1 && k < KD) ? rv : 0.f;
            float s = rp * rp;
            s += __shfl_xor_sync(FULL, s, 8);
            s += __shfl_xor_sync(FULL, s, 4);
            s += __shfl_xor_sync(FULL, s, 2);
            s += __shfl_xor_sync(FULL, s, 1);
            const float inv0 = (s > 1e-16f) ? rsqrtf(s) : 1e8f;
            float sn, cs;
            __sincosf(PI * zv, &sn, &cs);
            float v = sn * (rp * inv0);
            if (k == 0) v -= cs;
            const bool active = (n >= 1 && n <= 64);
            vv[q] = active ? v : ((n == 0) ? ((k == 0) ? 1.f : 0.f) : 0.f);
        }
        Vp[jp] = pack2(vv[0], vv[1]);
    }

    // ---- prologue ----
    float P;
    {
        ulonglong2 w0[9];
        const ulonglong2* cr = (const ulonglong2*)(Csh + 1 * CST + HALF * h);
#pragma unroll
        for (int c = 0; c < 9; ++c) w0[c] = cr[c];
        const float acc = dot_regs(w0, Vp);
        P = acc + __shfl_xor_sync(FULL, acc, 16);
    }
    // preload row for step 1's dot target (row inext=2) and its scalar
    ulonglong2 rowA[9];
    {
        const ulonglong2* cr = (const ulonglong2*)(Csh + 2 * CST + HALF * h);
#pragma unroll
        for (int c = 0; c < 9; ++c) rowA[c] = cr[c];
    }
    float c_cur = Csh[2 * CST + 1];   // C[2][1]
    float t = 0.f, inv = 0.f;

    // ---- pipelined sweeps ----
    for (int it = 0; it < miter; ++it) {
#pragma unroll
        for (int i = 1; i < NV1; ++i) {
            const int hi = (i < HALF) ? 0 : 1;    // owning half of coord i
            const int ji = i - HALF * hi;         // element slot in owner
            const int jp = ji >> 1;               // packed slot (compile-time)
            const int inext  = (i < 64) ? i + 1 : 1;
            const int innext = (i <= 62) ? i + 2 : i - 62;   // 63->1, 64->2

            // ---- (1) prefetch row(innext) + scalar for NEXT step ----------
            ulonglong2 rowN[9];
            {
                const ulonglong2* cr = (const ulonglong2*)(Csh + innext * CST + HALF * h);
#pragma unroll
                for (int c = 0; c < 9; ++c) rowN[c] = cr[c];
            }
            const float c_next = Csh[innext * CST + inext];  // C[i+2][i+1]

            // ---- (2) critical chain: g, ||g||^2 ---------------------------
            const float g = fmaf(t, inv, P);

            const float c1 = __shfl_xor_sync(FULL, g, 4);
            const float c2 = __shfl_xor_sync(FULL, g, 8);
            const float c3 = __shfl_xor_sync(FULL, g, 12);
            float s4 = g * g;
            s4 = fmaf(c1, c1, s4);
            s4 = fmaf(c2, c2, s4);
            s4 = fmaf(c3, c3, s4);
            const float d1 = __shfl_xor_sync(FULL, s4, 1);
            const float d2 = __shfl_xor_sync(FULL, s4, 2);
            const float d3 = __shfl_xor_sync(FULL, s4, 3);
            float s = (s4 + d1) + (d2 + d3);
            s = fmaxf(s, 1e-16f);

            // ---- (3) off-chain: dot with PRELOADED row (no LDS stall) -----
            t = -c_cur * g;                                  // pending coeff

            float acc = dot_regs(rowA, Vp);
            float vx, vy;
            if (h == hi) {
                unpack2(Vp[jp], vx, vy);
                const float vold = (ji & 1) ? vy : vx;
                acc = fmaf(-c_cur, vold, acc);               // remove OLD V[i]
            }
            P = acc + __shfl_xor_sync(FULL, acc, 16);

            // ---- (4) finish chain, commit v_i ------------------------------
            inv = rsqrtf(s);
            const float v = -g * inv;
            if (h == hi) {
                if (ji & 1) Vp[jp] = pack2(vx, v);
                else        Vp[jp] = pack2(v, vy);
            }

            // ---- rotate pipeline (renamed away in unrolled code) -----------
#pragma unroll
            for (int c = 0; c < 9; ++c) rowA[c] = rowN[c];
            c_cur = c_next;
        }
    }

    // ---- output: out[b][n-1] = acos(clip(-V[0][n])) / pi ----
    if (k == 0) {
#pragma unroll
        for (int jp = 0; jp < NP; ++jp) {
            float vals[2];
            unpack2(Vp[jp], vals[0], vals[1]);
#pragma unroll
            for (int q = 0; q < 2; ++q) {
                const int n = HALF * h + 2 * jp + q;
                if (n >= 1 && n <= 64) {
                    float c = -vals[q];
                    c = fminf(fmaxf(c, -1.f + 1e-6f), 1.f - 1e-6f);
                    out[b * N_VARS + (n - 1)] = acosf(c) * (1.0f / PI);
                }
            }
        }
    }
}

// ---------------------------------------------------------------------------
extern "C" void kernel_launch(void* const* d_in, const int* in_sizes, int n_in,
                              void* d_out, int out_size)
{
    const float* z = (const float*)d_in[0];
    const float* S = (const float*)d_in[1];
    const float* w = (const float*)d_in[2];
    const float* r = (const float*)d_in[3];
    const int* mi  = (n_in > 4) ? (const int*)d_in[4] : nullptr;
    float* out = (float*)d_out;

    const int B = in_sizes[0] / N_VARS;

    gram_kernel<<<NV1, CST>>>(S, w);
    mix_kernel<<<(B + 3) / 4, 128>>>(z, r, mi, out, B);
}

// round 11
// speedup vs baseline: 1.4524x; 1.0078x over previous
#include <cuda_runtime.h>
#include <math.h>

#define N_VARS 64
#define NV1    65      // N = n_vars + 1
#define M_CL   256
#define KD     12
#define CST    72      // padded C row stride in floats (cols 65..71 zero)
#define HALF   36      // n-range width per lane-half
#define NP     18      // f32x2 pairs per half

// Gram matrix C = Sw^T Sw with ZEROED DIAGONAL, padded rows
__device__ __align__(16) float g_C[NV1 * CST];

typedef unsigned long long u64;

// ---- packed f32x2 primitives (pure PTX, operands stay in u64 pairs) --------
__device__ __forceinline__ u64 ffma2u(u64 a, u64 b, u64 c)
{
    u64 d;
    asm("fma.rn.f32x2 %0, %1, %2, %3;" : "=l"(d) : "l"(a), "l"(b), "l"(c));
    return d;
}
__device__ __forceinline__ u64 fadd2u(u64 a, u64 b)
{
    u64 d;
    asm("add.rn.f32x2 %0, %1, %2;" : "=l"(d) : "l"(a), "l"(b));
    return d;
}
__device__ __forceinline__ u64 pack2(float x, float y)
{
    u64 d;
    asm("mov.b64 %0, {%1, %2};" : "=l"(d) : "f"(x), "f"(y));
    return d;
}
__device__ __forceinline__ void unpack2(u64 p, float& x, float& y)
{
    asm("mov.b64 {%0, %1}, %2;" : "=f"(x), "=f"(y) : "l"(p));
}

// packed dot of one 36-wide C-row half with packed V
__device__ __forceinline__ float dot_half(const float* __restrict__ rowF,
                                          const u64* __restrict__ Vp)
{
    const ulonglong2* cr = (const ulonglong2*)rowF;    // 16B-aligned (CST=72, HALF=36)
    u64 a0 = 0ull, a1 = 0ull, a2 = 0ull, a3 = 0ull;
#pragma unroll
    for (int c = 0; c < 9; ++c) {
        const ulonglong2 cv = cr[c];
        if (c & 1) { a2 = ffma2u(cv.x, Vp[2*c+0], a2); a3 = ffma2u(cv.y, Vp[2*c+1], a3); }
        else       { a0 = ffma2u(cv.x, Vp[2*c+0], a0); a1 = ffma2u(cv.y, Vp[2*c+1], a1); }
    }
    const u64 tt = fadd2u(fadd2u(a0, a2), fadd2u(a1, a3));
    float x, y; unpack2(tt, x, y);
    return x + y;
}

// ---------------------------------------------------------------------------
// Kernel 1: C[i][j] = sum_m (S[m,i]*w[m]) * (S[m,j]*w[m]);  C[i][i] = 0
// ---------------------------------------------------------------------------
__global__ void gram_kernel(const float* __restrict__ S, const float* __restrict__ w)
{
    const int i = blockIdx.x;    // 0..64
    const int j = threadIdx.x;   // 0..71
    float acc = 0.f;
    if (j < NV1) {
#pragma unroll 16
        for (int m = 0; m < M_CL; ++m) {
            const float wm = __ldg(&w[m]);
            acc = fmaf(__ldg(&S[m * NV1 + i]) * wm, __ldg(&S[m * NV1 + j]) * wm, acc);
        }
    }
    g_C[i * CST + j] = (j < NV1 && j != i) ? acc : 0.f;
}

// ---------------------------------------------------------------------------
// Kernel 2: pipelined coordinate descent (R5 structure). One warp per batch.
// Lane = h*16 + k, k in [0,12) active, h in {0,1}.
// Lane (h,k) holds V[k][n] for n in [36h, 36h+36) as 18 packed f32x2 regs.
// Recurrence: g_i = P_i + C[i,i-1]*v_{i-1}  =>  g = fma(t, inv, P)
// Norm: MIO-minimal chained butterfly (combine + xor 8/4/2/1 = 5 shfls).
// ---------------------------------------------------------------------------
__global__ void __launch_bounds__(128, 1)
mix_kernel(const float* __restrict__ z, const float* __restrict__ r,
           const int* __restrict__ miter_p, float* __restrict__ out, int B)
{
    __shared__ __align__(16) float Csh[NV1 * CST];   // 18,720 B
    {
        const float4* src = (const float4*)g_C;
        float4* dst = (float4*)Csh;
#pragma unroll 4
        for (int t = threadIdx.x; t < (NV1 * CST) / 4; t += 128) dst[t] = src[t];
    }
    __syncthreads();

    const int lane = threadIdx.x & 31;
    const int warp = threadIdx.x >> 5;
    const int b    = blockIdx.x * 4 + warp;
    if (b >= B) return;

    const int k = lane & 15;      // component index (0..11 active)
    const int h = lane >> 4;      // which n-half
    const unsigned FULL = 0xffffffffu;
    const float PI = 3.14159265358979323846f;
    const int miter = miter_p ? *miter_p : 12;

    u64 Vp[NP];                   // packed V: pair jp = (n=36h+2jp, n+1)

    // ---- init: V[0]=e0; V[n] = -cos(pi z)e0 + sin(pi z) r_perp_hat ----
#pragma unroll
    for (int jp = 0; jp < NP; ++jp) {
        float vv[2];
#pragma unroll
        for (int q = 0; q < 2; ++q) {
            const int j  = 2 * jp + q;
            const int n  = HALF * h + j;
            const int nc = (n < 1) ? 1 : ((n > 64) ? 64 : n);
            const float zv = z[b * N_VARS + nc - 1];
            const float rv = r[(b * N_VARS + nc - 1) * KD + ((k < KD) ? k : 0)];
            const float rp = (k >= 1 && k < KD) ? rv : 0.f;
            float s = rp * rp;
            s += __shfl_xor_sync(FULL, s, 8);
            s += __shfl_xor_sync(FULL, s, 4);
            s += __shfl_xor_sync(FULL, s, 2);
            s += __shfl_xor_sync(FULL, s, 1);
            const float inv0 = (s > 1e-16f) ? rsqrtf(s) : 1e8f;
            float sn, cs;
            __sincosf(PI * zv, &sn, &cs);
            float v = sn * (rp * inv0);
            if (k == 0) v -= cs;
            const bool active = (n >= 1 && n <= 64);
            vv[q] = active ? v : ((n == 0) ? ((k == 0) ? 1.f : 0.f) : 0.f);
        }
        Vp[jp] = pack2(vv[0], vv[1]);
    }

    // ---- pipelined sweeps ----
    float P, t = 0.f, inv = 0.f;

    // prologue: P = full dot of row 1 (no pending coordinate)
    {
        const float acc = dot_half(Csh + 1 * CST + HALF * h, Vp);
        P = acc + __shfl_xor_sync(FULL, acc, 16);
    }

    for (int it = 0; it < miter; ++it) {
#pragma unroll
        for (int i = 1; i < NV1; ++i) {
            const int hi = (i < HALF) ? 0 : 1;    // owning half of coord i
            const int ji = i - HALF * hi;         // element slot in owner
            const int jp = ji >> 1;               // packed slot (compile-time)
            const int inext = (i < 64) ? i + 1 : 1;

            // -------- critical chain: g, ||g||^2 (chained butterfly) --------
            const float g = fmaf(t, inv, P);

            float s = g * g;
            s += __shfl_xor_sync(FULL, s, 8);
            s += __shfl_xor_sync(FULL, s, 4);
            s += __shfl_xor_sync(FULL, s, 2);
            s += __shfl_xor_sync(FULL, s, 1);
            s = fmaxf(s, 1e-16f);

            // -------- off-chain: next-row packed dot --------
            const float cni = Csh[inext * CST + i];   // C[inext][i]
            t = -cni * g;                             // pending-term coeff

            float acc = dot_half(Csh + inext * CST + HALF * h, Vp);

            float vx, vy;
            if (h == hi) {
                unpack2(Vp[jp], vx, vy);
                const float vold = (ji & 1) ? vy : vx;
                acc = fmaf(-cni, vold, acc);          // remove OLD V[i] term
            }
            P = acc + __shfl_xor_sync(FULL, acc, 16);

            // -------- finish chain, commit v_i --------
            inv = rsqrtf(s);
            const float v = -g * inv;
            if (h == hi) {                            // compile-time slot
                if (ji & 1) Vp[jp] = pack2(vx, v);
                else        Vp[jp] = pack2(v, vy);
            }
        }
    }

    // ---- output: out[b][n-1] = acos(clip(-V[0][n])) / pi ----
    if (k == 0) {
#pragma unroll
        for (int jp = 0; jp < NP; ++jp) {
            float vals[2];
            unpack2(Vp[jp], vals[0], vals[1]);
#pragma unroll
            for (int q = 0; q < 2; ++q) {
                const int n = HALF * h + 2 * jp + q;
                if (n >= 1 && n <= 64) {
                    float c = -vals[q];
                    c = fminf(fmaxf(c, -1.f + 1e-6f), 1.f - 1e-6f);
                    out[b * N_VARS + (n - 1)] = acosf(c) * (1.0f / PI);
                }
            }
        }
    }
}

// ---------------------------------------------------------------------------
extern "C" void kernel_launch(void* const* d_in, const int* in_sizes, int n_in,
                              void* d_out, int out_size)
{
    const float* z = (const float*)d_in[0];
    const float* S = (const float*)d_in[1];
    const float* w = (const float*)d_in[2];
    const float* r = (const float*)d_in[3];
    const int* mi  = (n_in > 4) ? (const int*)d_in[4] : nullptr;
    float* out = (float*)d_out;

    const int B = in_sizes[0] / N_VARS;

    gram_kernel<<<NV1, CST>>>(S, w);
    mix_kernel<<<(B + 3) / 4, 128>>>(z, r, mi, out, B);
}